// round 16
// baseline (speedup 1.0000x reference)
#include <cuda_runtime.h>
#include <cuda_fp16.h>
#include <cstdint>

#define HW 256
#define BATCH 8
#define EPSV 1e-8f
#define INV_SQRT2 0.70710678118654752440f

// ---------------- scratch (fp16 NHWC, channel-interleaved per 16) ----------------
__device__ __align__(1024) __half g_t[(size_t)BATCH * HW * HW * 128];
__device__ __align__(1024) __half g_xact[(size_t)BATCH * HW * HW * 64];
__device__ __align__(1024) __half g_xraw[(size_t)BATCH * HW * HW * 64];
__device__ __align__(1024) __half g_w1h[4 * 9 * 2048];
__device__ __align__(1024) __half g_w2h[8 * 9 * 2048];
__device__ __align__(1024) __half g_wsch[BATCH * 4 * 2048];
__device__ float g_style1[BATCH * 64];
__device__ float g_style2[BATCH * 128];
__device__ float g_d1[BATCH * 128];
__device__ float g_d2[BATCH * 128];
__device__ float g_d2inv[BATCH * 128];

#define IN_WORDS 1600              // 10 rows * 10 pair-slots * 16 words
#define SCIN_WORDS 1024            // 8 rows * 8 pair-slots * 16 words
#define W_WORDS 9216               // 9 taps * 1024 words
#define SCW_WORDS 1024
#define OFF_SCIN IN_WORDS
#define OFF_W (IN_WORDS + SCIN_WORDS)              // 2624
#define OFF_SCW (OFF_W + W_WORDS)                  // 11840
#define BUF_WORDS (OFF_SCW + SCW_WORDS)            // 12864
#define MBAR_OFF (2 * BUF_WORDS)
#define SMEM_BYTES (2 * BUF_WORDS * 4 + 16)

__device__ __forceinline__ float lrelu(float v) { return v > 0.f ? v : 0.2f * v; }
// storage index p (0..15) -> channel within 16-group
__device__ __forceinline__ int perm16(int p) {
    return 2 * (p >> 2) + (p & 1) + 8 * ((p >> 1) & 1);
}
// weight half-position within a 2048-half tap block for (co, p)
__device__ __forceinline__ int wpos(int co, int p) {
    return ((co >> 4) * 8 + (co & 7)) * 32 + (p >> 2) * 8 + ((co >> 3) & 1) * 4 + (p & 3);
}

__device__ __forceinline__ void mma16(float c[4], unsigned a0, unsigned a1,
                                      unsigned a2, unsigned a3, unsigned b0, unsigned b1) {
    asm("mma.sync.aligned.m16n8k16.row.col.f32.f16.f16.f32 "
        "{%0,%1,%2,%3},{%4,%5,%6,%7},{%8,%9},{%0,%1,%2,%3};"
        : "+f"(c[0]), "+f"(c[1]), "+f"(c[2]), "+f"(c[3])
        : "r"(a0), "r"(a1), "r"(a2), "r"(a3), "r"(b0), "r"(b1));
}

__device__ __forceinline__ void cpa8z(uint32_t dst, const void* src, bool inb) {
    int sz = inb ? 8 : 0;
    asm volatile("cp.async.ca.shared.global [%0], [%1], 8, %2;"
                 :: "r"(dst), "l"(src), "r"(sz));
}
__device__ __forceinline__ void cp_commit() { asm volatile("cp.async.commit_group;"); }
__device__ __forceinline__ void cp_wait0() { asm volatile("cp.async.wait_group 0;"); }

__device__ __forceinline__ void mbar_init(uint32_t m, uint32_t cnt) {
    asm volatile("mbarrier.init.shared.b64 [%0], %1;" :: "r"(m), "r"(cnt) : "memory");
}
__device__ __forceinline__ void mbar_expect(uint32_t m, uint32_t bytes) {
    asm volatile("mbarrier.arrive.expect_tx.shared.b64 _, [%0], %1;"
                 :: "r"(m), "r"(bytes) : "memory");
}
__device__ __forceinline__ void mbar_wait(uint32_t m, uint32_t phase) {
    uint32_t done = 0;
    while (!done)
        asm volatile(
            "{\n\t.reg .pred p;\n\t"
            "mbarrier.try_wait.parity.acquire.cta.shared::cta.b64 p, [%1], %2, 0x989680;\n\t"
            "selp.b32 %0, 1, 0, p;\n\t}"
            : "=r"(done) : "r"(m), "r"(phase) : "memory");
}
__device__ __forceinline__ void cp_bulk(uint32_t dst, const void* src,
                                        uint32_t bytes, uint32_t mbar) {
    asm volatile(
        "cp.async.bulk.shared::cta.global.mbarrier::complete_tx::bytes [%0], [%1], %2, [%3];"
        :: "r"(dst), "l"(src), "r"(bytes), "r"(mbar) : "memory");
}

// ---------------- fused style + demod ----------------
__global__ __launch_bounds__(256)
void style_demod_kernel(const float* __restrict__ s,
                        const float* __restrict__ a1w, const float* __restrict__ a1b,
                        const float* __restrict__ a2w, const float* __restrict__ a2b,
                        const float* __restrict__ w1, const float* __restrict__ w2) {
    int b = blockIdx.x, t = threadIdx.x;
    __shared__ float sh[64];
    __shared__ float st1[64];
    __shared__ float st2[128];
    if (t < 64) sh[t] = s[b * 64 + t];
    __syncthreads();
    if (t < 64) {
        float a = a1b[t];
        #pragma unroll 4
        for (int j2 = 0; j2 < 64; j2++) a += sh[j2] * a1w[t * 64 + j2];
        st1[t] = a + 1.f;
        if (blockIdx.y == 0) g_style1[b * 64 + t] = a + 1.f;
    }
    if (t < 128) {
        float a = a2b[t];
        #pragma unroll 4
        for (int j2 = 0; j2 < 64; j2++) a += sh[j2] * a2w[t * 64 + j2];
        st2[t] = a + 1.f;
        if (blockIdx.y == 0) g_style2[b * 128 + t] = a + 1.f;
    }
    __syncthreads();
    int co = blockIdx.y * 8 + (t >> 5);
    int lane = t & 31;
    float s1 = 0.f;
    for (int e = lane; e < 64 * 9; e += 32) {
        float wv = w1[co * 64 * 9 + e];
        float st = st1[e / 9];
        s1 += wv * wv * st * st;
    }
    #pragma unroll
    for (int o = 16; o; o >>= 1) s1 += __shfl_xor_sync(0xffffffffu, s1, o);
    if (lane == 0) g_d1[b * 128 + co] = rsqrtf(s1 + EPSV);
    float s2 = 0.f;
    for (int e = lane; e < 128 * 9; e += 32) {
        float wv = w2[co * 128 * 9 + e];
        float st = st2[e / 9];
        s2 += wv * wv * st * st;
    }
    #pragma unroll
    for (int o = 16; o; o >>= 1) s2 += __shfl_xor_sync(0xffffffffu, s2, o);
    if (lane == 0) {
        float d = rsqrtf(s2 + EPSV);
        g_d2[b * 128 + co] = d;
        g_d2inv[b * 128 + co] = 1.f / d;
    }
}

// NCHW fp32 x -> NHWC fp16 (activated+styled, and raw), channel-permuted per 16
__global__ __launch_bounds__(256) void act_kernel(const float* __restrict__ x) {
    __shared__ float sa[64][65];
    __shared__ float sr[64][65];
    int t = threadIdx.x;
    int b = blockIdx.z, y = blockIdx.y, x0 = blockIdx.x * 64;
    {
        int ci = t >> 2, q = t & 3;
        const float* src = x + ((size_t)(b * 64 + ci) * 65536) + y * 256 + x0 + q * 16;
        float st = g_style1[b * 64 + ci];
        #pragma unroll
        for (int k = 0; k < 4; k++) {
            float4 v = *(const float4*)(src + k * 4);
            float rw[4] = {v.x, v.y, v.z, v.w};
            #pragma unroll
            for (int e = 0; e < 4; e++) {
                int xx = q * 16 + k * 4 + e;
                sr[ci][xx] = rw[e];
                sa[ci][xx] = lrelu(rw[e]) * st;
            }
        }
    }
    __syncthreads();
    int px = t >> 2, q = t & 3;   // q = 16-channel chunk
    size_t base = ((size_t)((b * 256 + y) * 256) + x0 + px) * 64 + q * 16;
    unsigned oa[8], orr[8];
    #pragma unroll
    for (int w = 0; w < 8; w++) {
        int ci0 = q * 16 + 2 * (w >> 1) + 8 * (w & 1);
        __half2 ha = __floats2half2_rn(sa[ci0][px], sa[ci0 + 1][px]);
        __half2 hr = __floats2half2_rn(sr[ci0][px], sr[ci0 + 1][px]);
        oa[w] = *(unsigned*)&ha;
        orr[w] = *(unsigned*)&hr;
    }
    *(uint4*)(g_xact + base)     = make_uint4(oa[0], oa[1], oa[2], oa[3]);
    *(uint4*)(g_xact + base + 8) = make_uint4(oa[4], oa[5], oa[6], oa[7]);
    *(uint4*)(g_xraw + base)     = make_uint4(orr[0], orr[1], orr[2], orr[3]);
    *(uint4*)(g_xraw + base + 8) = make_uint4(orr[4], orr[5], orr[6], orr[7]);
}

// weights -> [chunk][tap]{pos(co,p)} fp16 (ci permuted; co-pair interleaved for LDS.128)
template <bool FIRST>
__global__ void prep_w(const float* __restrict__ w) {
    const int CIN = FIRST ? 64 : 128;
    int idx = blockIdx.x * 256 + threadIdx.x;
    if (idx >= (CIN / 16) * 9 * 128 * 16) return;
    int chk = idx / 18432, rem = idx % 18432;
    int tap = rem / 2048, rem2 = rem & 2047;
    int co = rem2 >> 4, p = rem2 & 15;
    int ci = chk * 16 + perm16(p);
    int dst = (chk * 9 + tap) * 2048 + wpos(co, p);
    (FIRST ? g_w1h : g_w2h)[dst] = __float2half_rn(w[(co * CIN + ci) * 9 + tap]);
}

__global__ void prep_sc(const float* __restrict__ scw) {
    int idx = blockIdx.x * 256 + threadIdx.x;   // 65536
    int b = idx >> 13, rem = idx & 8191;
    int chk = rem >> 11;
    int co = (rem >> 4) & 127, p = rem & 15;
    int ci = chk * 16 + perm16(p);
    int dst = (b * 4 + chk) * 2048 + wpos(co, p);
    g_wsch[dst] = __float2half_rn(scw[co * 64 + ci] * g_d2inv[b * 128 + co]);
}

// ---------------- fp16 implicit-GEMM conv ----------------
// CTA: 128 px (8y x 16x) x 128 co, 128 threads. warp: 4y x 16x x 64 co.
// A tile as (x,x+8) pair slots -> one LDS.128 = a0..a3; B co-pair interleaved.
// conv2: shortcut fused into steps 0..3 (10th tap), 8 pipeline rounds total.
template <int CIN, bool FIRST>
__global__ __launch_bounds__(128, 2)
void conv_fp16(const float* __restrict__ noise, const float* __restrict__ nwp,
               float* __restrict__ outp) {
    extern __shared__ __align__(16) unsigned smem[];
    const uint32_t smem_u32 = (uint32_t)__cvta_generic_to_shared(smem);
    const uint32_t mbar0 = smem_u32 + MBAR_OFF * 4;

    const int tid = threadIdx.x, lane = tid & 31, wrp = tid >> 5;
    const int wm = wrp & 1, wn = wrp >> 1;
    const int j = lane & 3, r = lane >> 2;
    const int b = blockIdx.z;
    const int py0 = blockIdx.y * 8, px0 = blockIdx.x * 16;
    const int TOT = CIN / 16;                   // 4 (conv1) or 8 (conv2)

    const __half* src = FIRST ? g_xact : g_t;
    const __half* wsrc = FIRST ? g_w1h : g_w2h;

    if (tid == 0) {
        mbar_init(mbar0, 1);
        mbar_init(mbar0 + 8, 1);
    }
    __syncthreads();

    float acc[4][8][4];
    #pragma unroll
    for (int m = 0; m < 4; m++)
        #pragma unroll
        for (int n = 0; n < 8; n++)
            #pragma unroll
            for (int q = 0; q < 4; q++) acc[m][n][q] = 0.f;

    auto issue = [&](int s, int buf) {
        uint32_t in_base = smem_u32 + (uint32_t)(buf * BUF_WORDS) * 4;
        uint32_t mb = mbar0 + 8 * buf;
        // main chunk: 10 rows x 10 pair-slots, 8B pieces
        #pragma unroll
        for (int t2 = 0; t2 < 7; t2++) {
            int idx = tid + t2 * 128;
            if (idx < 800) {
                int row = idx / 80, rm = idx - row * 80;
                int pr = rm >> 3, q3 = rm & 7;
                int kk = q3 >> 1, hf = q3 & 1;
                int xx = pr + hf * 8;
                int gy = py0 - 1 + row, gx = px0 - 1 + xx;
                bool inb = ((unsigned)gy < HW) && ((unsigned)gx < HW);
                const __half* sp = src + (size_t)((b * 256 + gy) * 256 + gx) * CIN
                                   + s * 16 + kk * 4;
                cpa8z(in_base + (uint32_t)((row * 10 + pr) * 16 + kk * 4 + hf * 2) * 4,
                      sp, inb);
            }
        }
        bool has_sc = (!FIRST) && (s < 4);
        if (has_sc) {
            // fused shortcut chunk s: 8 rows x 8 pair-slots
            #pragma unroll
            for (int t2 = 0; t2 < 4; t2++) {
                int idx = tid + t2 * 128;       // 512 pieces
                int pix = idx >> 2, kk = idx & 3;
                int row = pix >> 4, xx = pix & 15;
                int c = xx & 7, hf = xx >> 3;
                const __half* sp = g_xraw
                    + (size_t)((b * 256 + py0 + row) * 256 + px0 + xx) * 64
                    + s * 16 + kk * 4;
                cpa8z(in_base + (uint32_t)(OFF_SCIN + (row * 8 + c) * 16 + kk * 4 + hf * 2) * 4,
                      sp, true);
            }
        }
        if (tid == 0) {
            mbar_expect(mb, has_sc ? 40960u : 36864u);
            cp_bulk(in_base + OFF_W * 4, (const char*)wsrc + (size_t)s * 36864, 36864, mb);
            if (has_sc)
                cp_bulk(in_base + OFF_SCW * 4,
                        (const char*)g_wsch + (size_t)(b * 4 + s) * 4096, 4096, mb);
        }
        cp_commit();
    };

    issue(0, 0);
    for (int s = 0; s < TOT; s++) {
        const int buf = s & 1;
        cp_wait0();
        mbar_wait(mbar0 + 8 * buf, (s >> 1) & 1);
        __syncthreads();
        if (s + 1 < TOT) issue(s + 1, buf ^ 1);

        const unsigned* s_in = smem + buf * BUF_WORDS;
        const unsigned* s_w = s_in + OFF_W;

        #pragma unroll
        for (int tap = 0; tap < 9; tap++) {
            const int dy = tap / 3, dx = tap - 3 * dy;
            uint4 bq[4];
            #pragma unroll
            for (int e = 0; e < 4; e++)
                bq[e] = *(const uint4*)(s_w + tap * 1024
                                        + ((wn * 4 + e) * 8 + r) * 16 + j * 4);
            #pragma unroll
            for (int mf = 0; mf < 4; mf++) {
                int arow = 4 * wm + mf + dy;
                uint4 aq = *(const uint4*)(s_in + (arow * 10 + r + dx) * 16 + j * 4);
                #pragma unroll
                for (int e = 0; e < 4; e++) {
                    mma16(acc[mf][2 * e],     aq.x, aq.z, aq.y, aq.w, bq[e].x, bq[e].y);
                    mma16(acc[mf][2 * e + 1], aq.x, aq.z, aq.y, aq.w, bq[e].z, bq[e].w);
                }
            }
        }
        if (!FIRST && s < 4) {
            const unsigned* s_scin = s_in + OFF_SCIN;
            const unsigned* s_scw = s_in + OFF_SCW;
            uint4 bq[4];
            #pragma unroll
            for (int e = 0; e < 4; e++)
                bq[e] = *(const uint4*)(s_scw + ((wn * 4 + e) * 8 + r) * 16 + j * 4);
            #pragma unroll
            for (int mf = 0; mf < 4; mf++) {
                int arow = 4 * wm + mf;
                uint4 aq = *(const uint4*)(s_scin + (arow * 8 + r) * 16 + j * 4);
                #pragma unroll
                for (int e = 0; e < 4; e++) {
                    mma16(acc[mf][2 * e],     aq.x, aq.z, aq.y, aq.w, bq[e].x, bq[e].y);
                    mma16(acc[mf][2 * e + 1], aq.x, aq.z, aq.y, aq.w, bq[e].z, bq[e].w);
                }
            }
        }
    }

    // ---------------- epilogue ----------------
    const float nw = __ldg(nwp);
    float nz[4][2];
    #pragma unroll
    for (int mf = 0; mf < 4; mf++) {
        int gy = py0 + 4 * wm + mf;
        const float* np = noise + (size_t)b * 65536 + (size_t)gy * 256 + px0 + r;
        nz[mf][0] = nw * __ldg(np);
        nz[mf][1] = nw * __ldg(np + 8);
    }
    #pragma unroll
    for (int nf = 0; nf < 8; nf++) {
        int cp = wn * 64 + nf * 8 + 2 * j;       // even co of the pair
        float da, db, sa = 0.f, sb = 0.f;
        if (FIRST) {
            da = __ldg(g_d1 + b * 128 + cp); db = __ldg(g_d1 + b * 128 + cp + 1);
            sa = __ldg(g_style2 + b * 128 + cp); sb = __ldg(g_style2 + b * 128 + cp + 1);
        } else {
            da = __ldg(g_d2 + b * 128 + cp); db = __ldg(g_d2 + b * 128 + cp + 1);
        }
        #pragma unroll
        for (int mf = 0; mf < 4; mf++) {
            int gy = py0 + 4 * wm + mf;
            float v0 = da * acc[mf][nf][0] + nz[mf][0];
            float v1 = db * acc[mf][nf][1] + nz[mf][0];
            float v2 = da * acc[mf][nf][2] + nz[mf][1];
            float v3 = db * acc[mf][nf][3] + nz[mf][1];
            if (FIRST) {
                int c16 = cp & 15;
                int word = 2 * ((c16 & 7) >> 1) + (c16 >> 3);
                size_t pb = ((size_t)((b * 256 + gy) * 256) + px0 + r) * 64
                            + (cp >> 4) * 8 + word;
                __half2 h0 = __floats2half2_rn(lrelu(v0) * sa, lrelu(v1) * sb);
                __half2 h2 = __floats2half2_rn(lrelu(v2) * sa, lrelu(v3) * sb);
                *(__half2*)((__half*)g_t + pb * 2) = h0;
                *(__half2*)((__half*)g_t + (pb + 8 * 64) * 2) = h2;
            } else {
                size_t ob = ((size_t)(b * 128 + cp) * 256 + gy) * 256 + px0 + r;
                outp[ob] = v0 * INV_SQRT2;
                outp[ob + 65536] = v1 * INV_SQRT2;
                outp[ob + 8] = v2 * INV_SQRT2;
                outp[ob + 65536 + 8] = v3 * INV_SQRT2;
            }
        }
    }
}

// ---------------- host ----------------
extern "C" void kernel_launch(void* const* d_in, const int* in_sizes, int n_in,
                              void* d_out, int out_size) {
    const float* x   = (const float*)d_in[0];
    const float* s   = (const float*)d_in[1];
    const float* noi = (const float*)d_in[2];
    const float* a1w = (const float*)d_in[3];
    const float* a1b = (const float*)d_in[4];
    const float* w1  = (const float*)d_in[5];
    const float* a2w = (const float*)d_in[6];
    const float* a2b = (const float*)d_in[7];
    const float* w2  = (const float*)d_in[8];
    const float* nw  = (const float*)d_in[9];
    const float* scw = (const float*)d_in[10];
    float* out = (float*)d_out;

    static bool attr_done = false;
    if (!attr_done) {
        cudaFuncSetAttribute(conv_fp16<64, true>,
                             cudaFuncAttributeMaxDynamicSharedMemorySize, SMEM_BYTES);
        cudaFuncSetAttribute(conv_fp16<128, false>,
                             cudaFuncAttributeMaxDynamicSharedMemorySize, SMEM_BYTES);
        attr_done = true;
    }

    // order chosen so conv1 is the 4th launch (ncu profiles launch #4)
    style_demod_kernel<<<dim3(BATCH, 16), 256>>>(s, a1w, a1b, a2w, a2b, w1, w2);
    prep_w<true><<<288, 256>>>(w1);
    act_kernel<<<dim3(4, 256, 8), 256>>>(x);

    dim3 grid(HW / 16, HW / 8, BATCH);
    conv_fp16<64, true><<<grid, 128, SMEM_BYTES>>>(noi, nw, nullptr);

    prep_w<false><<<576, 256>>>(w2);
    prep_sc<<<256, 256>>>(scw);
    conv_fp16<128, false><<<grid, 128, SMEM_BYTES>>>(noi, nw, out);
}

// round 17
// speedup vs baseline: 1.0796x; 1.0796x over previous
#include <cuda_runtime.h>
#include <cuda_fp16.h>
#include <cstdint>

#define HW 256
#define BATCH 8
#define EPSV 1e-8f
#define INV_SQRT2 0.70710678118654752440f

// ---------------- scratch (fp16 NHWC, channel-interleaved per 16) ----------------
__device__ __align__(1024) __half g_t[(size_t)BATCH * HW * HW * 128];
__device__ __align__(1024) __half g_xact[(size_t)BATCH * HW * HW * 64];
__device__ __align__(1024) __half g_xraw[(size_t)BATCH * HW * HW * 64];
__device__ __align__(1024) __half g_w1h[4 * 9 * 2048];
__device__ __align__(1024) __half g_w2h[8 * 9 * 2048];
__device__ __align__(1024) __half g_wsch[BATCH * 4 * 2048];
__device__ float g_style1[BATCH * 64];
__device__ float g_style2[BATCH * 128];
__device__ float g_d1[BATCH * 128];
__device__ float g_d2[BATCH * 128];
__device__ float g_d2inv[BATCH * 128];

#define IN_WORDS 1600              // 10 rows * 10 pair-slots * 16 words (64B/slot)
#define W_WORDS 9216               // 9 taps * 1024 words
#define BUF_WORDS (IN_WORDS + W_WORDS)
#define MBAR_OFF (2 * BUF_WORDS)
#define SMEM_BYTES (2 * BUF_WORDS * 4 + 16)

__device__ __forceinline__ float lrelu(float v) { return v > 0.f ? v : 0.2f * v; }
// storage index p (0..15) -> channel within 16-group
__device__ __forceinline__ int perm16(int p) {
    return 2 * (p >> 2) + (p & 1) + 8 * ((p >> 1) & 1);
}
// weight half-position within a 2048-half tap block for (co, p)
__device__ __forceinline__ int wpos(int co, int p) {
    return ((co >> 4) * 8 + (co & 7)) * 32 + (p >> 2) * 8 + ((co >> 3) & 1) * 4 + (p & 3);
}

__device__ __forceinline__ void mma16(float c[4], unsigned a0, unsigned a1,
                                      unsigned a2, unsigned a3, unsigned b0, unsigned b1) {
    asm("mma.sync.aligned.m16n8k16.row.col.f32.f16.f16.f32 "
        "{%0,%1,%2,%3},{%4,%5,%6,%7},{%8,%9},{%0,%1,%2,%3};"
        : "+f"(c[0]), "+f"(c[1]), "+f"(c[2]), "+f"(c[3])
        : "r"(a0), "r"(a1), "r"(a2), "r"(a3), "r"(b0), "r"(b1));
}

__device__ __forceinline__ void cpa8z(uint32_t dst, const void* src, bool inb) {
    int sz = inb ? 8 : 0;
    asm volatile("cp.async.ca.shared.global [%0], [%1], 8, %2;"
                 :: "r"(dst), "l"(src), "r"(sz));
}
__device__ __forceinline__ void cp_commit() { asm volatile("cp.async.commit_group;"); }
__device__ __forceinline__ void cp_wait0() { asm volatile("cp.async.wait_group 0;"); }

__device__ __forceinline__ void mbar_init(uint32_t m, uint32_t cnt) {
    asm volatile("mbarrier.init.shared.b64 [%0], %1;" :: "r"(m), "r"(cnt) : "memory");
}
__device__ __forceinline__ void mbar_expect(uint32_t m, uint32_t bytes) {
    asm volatile("mbarrier.arrive.expect_tx.shared.b64 _, [%0], %1;"
                 :: "r"(m), "r"(bytes) : "memory");
}
__device__ __forceinline__ void mbar_wait(uint32_t m, uint32_t phase) {
    uint32_t done = 0;
    while (!done)
        asm volatile(
            "{\n\t.reg .pred p;\n\t"
            "mbarrier.try_wait.parity.acquire.cta.shared::cta.b64 p, [%1], %2, 0x989680;\n\t"
            "selp.b32 %0, 1, 0, p;\n\t}"
            : "=r"(done) : "r"(m), "r"(phase) : "memory");
}
__device__ __forceinline__ void cp_bulk(uint32_t dst, const void* src,
                                        uint32_t bytes, uint32_t mbar) {
    asm volatile(
        "cp.async.bulk.shared::cta.global.mbarrier::complete_tx::bytes [%0], [%1], %2, [%3];"
        :: "r"(dst), "l"(src), "r"(bytes), "r"(mbar) : "memory");
}

// ---------------- fused style + demod ----------------
__global__ __launch_bounds__(256)
void style_demod_kernel(const float* __restrict__ s,
                        const float* __restrict__ a1w, const float* __restrict__ a1b,
                        const float* __restrict__ a2w, const float* __restrict__ a2b,
                        const float* __restrict__ w1, const float* __restrict__ w2) {
    int b = blockIdx.x, t = threadIdx.x;
    __shared__ float sh[64];
    __shared__ float st1[64];
    __shared__ float st2[128];
    if (t < 64) sh[t] = s[b * 64 + t];
    __syncthreads();
    if (t < 64) {
        float a = a1b[t];
        #pragma unroll 4
        for (int j2 = 0; j2 < 64; j2++) a += sh[j2] * a1w[t * 64 + j2];
        st1[t] = a + 1.f;
        if (blockIdx.y == 0) g_style1[b * 64 + t] = a + 1.f;
    }
    if (t < 128) {
        float a = a2b[t];
        #pragma unroll 4
        for (int j2 = 0; j2 < 64; j2++) a += sh[j2] * a2w[t * 64 + j2];
        st2[t] = a + 1.f;
        if (blockIdx.y == 0) g_style2[b * 128 + t] = a + 1.f;
    }
    __syncthreads();
    int co = blockIdx.y * 8 + (t >> 5);
    int lane = t & 31;
    float s1 = 0.f;
    for (int e = lane; e < 64 * 9; e += 32) {
        float wv = w1[co * 64 * 9 + e];
        float st = st1[e / 9];
        s1 += wv * wv * st * st;
    }
    #pragma unroll
    for (int o = 16; o; o >>= 1) s1 += __shfl_xor_sync(0xffffffffu, s1, o);
    if (lane == 0) g_d1[b * 128 + co] = rsqrtf(s1 + EPSV);
    float s2 = 0.f;
    for (int e = lane; e < 128 * 9; e += 32) {
        float wv = w2[co * 128 * 9 + e];
        float st = st2[e / 9];
        s2 += wv * wv * st * st;
    }
    #pragma unroll
    for (int o = 16; o; o >>= 1) s2 += __shfl_xor_sync(0xffffffffu, s2, o);
    if (lane == 0) {
        float d = rsqrtf(s2 + EPSV);
        g_d2[b * 128 + co] = d;
        g_d2inv[b * 128 + co] = 1.f / d;
    }
}

// NCHW fp32 x -> NHWC fp16 (activated+styled, and raw), channel-permuted per 16
__global__ __launch_bounds__(256) void act_kernel(const float* __restrict__ x) {
    __shared__ float sa[64][65];
    __shared__ float sr[64][65];
    int t = threadIdx.x;
    int b = blockIdx.z, y = blockIdx.y, x0 = blockIdx.x * 64;
    {
        int ci = t >> 2, q = t & 3;
        const float* src = x + ((size_t)(b * 64 + ci) * 65536) + y * 256 + x0 + q * 16;
        float st = g_style1[b * 64 + ci];
        #pragma unroll
        for (int k = 0; k < 4; k++) {
            float4 v = *(const float4*)(src + k * 4);
            float rw[4] = {v.x, v.y, v.z, v.w};
            #pragma unroll
            for (int e = 0; e < 4; e++) {
                int xx = q * 16 + k * 4 + e;
                sr[ci][xx] = rw[e];
                sa[ci][xx] = lrelu(rw[e]) * st;
            }
        }
    }
    __syncthreads();
    int px = t >> 2, q = t & 3;   // q = 16-channel chunk
    size_t base = ((size_t)((b * 256 + y) * 256) + x0 + px) * 64 + q * 16;
    unsigned oa[8], orr[8];
    #pragma unroll
    for (int w = 0; w < 8; w++) {
        int ci0 = q * 16 + 2 * (w >> 1) + 8 * (w & 1);
        __half2 ha = __floats2half2_rn(sa[ci0][px], sa[ci0 + 1][px]);
        __half2 hr = __floats2half2_rn(sr[ci0][px], sr[ci0 + 1][px]);
        oa[w] = *(unsigned*)&ha;
        orr[w] = *(unsigned*)&hr;
    }
    *(uint4*)(g_xact + base)     = make_uint4(oa[0], oa[1], oa[2], oa[3]);
    *(uint4*)(g_xact + base + 8) = make_uint4(oa[4], oa[5], oa[6], oa[7]);
    *(uint4*)(g_xraw + base)     = make_uint4(orr[0], orr[1], orr[2], orr[3]);
    *(uint4*)(g_xraw + base + 8) = make_uint4(orr[4], orr[5], orr[6], orr[7]);
}

// fused weight prep: blocks [0,288) -> w1, [288,864) -> w2, [864,1120) -> shortcut
__global__ __launch_bounds__(256)
void prep_all_kernel(const float* __restrict__ w1, const float* __restrict__ w2,
                     const float* __restrict__ scw) {
    int blk = blockIdx.x;
    if (blk < 288) {
        int idx = blk * 256 + threadIdx.x;
        if (idx >= 4 * 9 * 2048) return;
        int chk = idx / 18432, rem = idx % 18432;
        int tap = rem / 2048, rem2 = rem & 2047;
        int co = rem2 >> 4, p = rem2 & 15;
        int ci = chk * 16 + perm16(p);
        g_w1h[(chk * 9 + tap) * 2048 + wpos(co, p)] =
            __float2half_rn(w1[(co * 64 + ci) * 9 + tap]);
    } else if (blk < 864) {
        int idx = (blk - 288) * 256 + threadIdx.x;
        if (idx >= 8 * 9 * 2048) return;
        int chk = idx / 18432, rem = idx % 18432;
        int tap = rem / 2048, rem2 = rem & 2047;
        int co = rem2 >> 4, p = rem2 & 15;
        int ci = chk * 16 + perm16(p);
        g_w2h[(chk * 9 + tap) * 2048 + wpos(co, p)] =
            __float2half_rn(w2[(co * 128 + ci) * 9 + tap]);
    } else {
        int idx = (blk - 864) * 256 + threadIdx.x;   // 65536
        int b = idx >> 13, rem = idx & 8191;
        int chk = rem >> 11;
        int co = (rem >> 4) & 127, p = rem & 15;
        int ci = chk * 16 + perm16(p);
        g_wsch[(b * 4 + chk) * 2048 + wpos(co, p)] =
            __float2half_rn(scw[co * 64 + ci] * g_d2inv[b * 128 + co]);
    }
}

// ---------------- fp16 implicit-GEMM conv (R15 proven version) ----------------
// CTA: 128 px (8y x 16x) x 128 co, 128 threads. warp: 4y x 16x x 64 co.
// A tile stored as (x,x+8) pair slots (8B interleave) -> one LDS.128 = a0..a3.
// B stored co-pair interleaved -> one LDS.128 = b-frags for 2 nf.
template <int CIN, bool FIRST>
__global__ __launch_bounds__(128, 2)
void conv_fp16(const float* __restrict__ noise, const float* __restrict__ nwp,
               float* __restrict__ outp) {
    extern __shared__ __align__(16) unsigned smem[];
    const uint32_t smem_u32 = (uint32_t)__cvta_generic_to_shared(smem);
    const uint32_t mbar0 = smem_u32 + MBAR_OFF * 4;

    const int tid = threadIdx.x, lane = tid & 31, wrp = tid >> 5;
    const int wm = wrp & 1, wn = wrp >> 1;
    const int j = lane & 3, r = lane >> 2;
    const int b = blockIdx.z;
    const int py0 = blockIdx.y * 8, px0 = blockIdx.x * 16;
    const int CCH = CIN / 16;
    const int TOT = FIRST ? CCH : CCH + 4;

    const __half* src = FIRST ? g_xact : g_t;
    const __half* wsrc = FIRST ? g_w1h : g_w2h;

    if (tid == 0) {
        mbar_init(mbar0, 1);
        mbar_init(mbar0 + 8, 1);
    }
    __syncthreads();

    float acc[4][8][4];
    #pragma unroll
    for (int m = 0; m < 4; m++)
        #pragma unroll
        for (int n = 0; n < 8; n++)
            #pragma unroll
            for (int q = 0; q < 4; q++) acc[m][n][q] = 0.f;

    auto issue = [&](int s, int buf) {
        uint32_t in_base = smem_u32 + (uint32_t)(buf * BUF_WORDS) * 4;
        uint32_t w_base = in_base + IN_WORDS * 4;
        uint32_t mb = mbar0 + 8 * buf;
        if (FIRST || s < CCH) {
            // main chunk: 10 rows x 10 pair-slots, 8B pieces
            #pragma unroll
            for (int t2 = 0; t2 < 7; t2++) {
                int idx = tid + t2 * 128;
                if (idx < 800) {
                    int row = idx / 80, rm = idx - row * 80;
                    int pr = rm >> 3, q3 = rm & 7;
                    int kk = q3 >> 1, hf = q3 & 1;
                    int xx = pr + hf * 8;
                    int gy = py0 - 1 + row, gx = px0 - 1 + xx;
                    bool inb = ((unsigned)gy < HW) && ((unsigned)gx < HW);
                    const __half* sp = src + (size_t)((b * 256 + gy) * 256 + gx) * CIN
                                       + s * 16 + kk * 4;
                    cpa8z(in_base + (uint32_t)((row * 10 + pr) * 16 + kk * 4 + hf * 2) * 4,
                          sp, inb);
                }
            }
            if (tid == 0) {
                mbar_expect(mb, 36864);
                cp_bulk(w_base, (const char*)wsrc + (size_t)s * 36864, 36864, mb);
            }
        } else {
            // shortcut chunk: 8 rows x 8 pair-slots (no halo)
            int sc = s - CCH;
            #pragma unroll
            for (int t2 = 0; t2 < 4; t2++) {
                int idx = tid + t2 * 128;       // 512 pieces
                int pix = idx >> 2, kk = idx & 3;
                int row = pix >> 4, xx = pix & 15;
                int c = xx & 7, hf = xx >> 3;
                const __half* sp = g_xraw
                    + (size_t)((b * 256 + py0 + row) * 256 + px0 + xx) * 64
                    + sc * 16 + kk * 4;
                cpa8z(in_base + (uint32_t)((row * 8 + c) * 16 + kk * 4 + hf * 2) * 4,
                      sp, true);
            }
            if (tid == 0) {
                mbar_expect(mb, 4096);
                cp_bulk(w_base, (const char*)g_wsch + (size_t)(b * 4 + sc) * 4096, 4096, mb);
            }
        }
        cp_commit();
    };

    issue(0, 0);
    for (int s = 0; s < TOT; s++) {
        const int buf = s & 1;
        cp_wait0();
        mbar_wait(mbar0 + 8 * buf, (s >> 1) & 1);
        __syncthreads();
        if (s + 1 < TOT) issue(s + 1, buf ^ 1);

        const unsigned* s_in = smem + buf * BUF_WORDS;
        const unsigned* s_w = s_in + IN_WORDS;

        if (FIRST || s < CCH) {
            #pragma unroll
            for (int tap = 0; tap < 9; tap++) {
                const int dy = tap / 3, dx = tap - 3 * dy;
                uint4 bq[4];
                #pragma unroll
                for (int e = 0; e < 4; e++)
                    bq[e] = *(const uint4*)(s_w + tap * 1024
                                            + ((wn * 4 + e) * 8 + r) * 16 + j * 4);
                #pragma unroll
                for (int mf = 0; mf < 4; mf++) {
                    int arow = 4 * wm + mf + dy;
                    uint4 aq = *(const uint4*)(s_in + (arow * 10 + r + dx) * 16 + j * 4);
                    #pragma unroll
                    for (int e = 0; e < 4; e++) {
                        mma16(acc[mf][2 * e],     aq.x, aq.z, aq.y, aq.w, bq[e].x, bq[e].y);
                        mma16(acc[mf][2 * e + 1], aq.x, aq.z, aq.y, aq.w, bq[e].z, bq[e].w);
                    }
                }
            }
        } else {
            uint4 bq[4];
            #pragma unroll
            for (int e = 0; e < 4; e++)
                bq[e] = *(const uint4*)(s_w + ((wn * 4 + e) * 8 + r) * 16 + j * 4);
            #pragma unroll
            for (int mf = 0; mf < 4; mf++) {
                int arow = 4 * wm + mf;
                uint4 aq = *(const uint4*)(s_in + (arow * 8 + r) * 16 + j * 4);
                #pragma unroll
                for (int e = 0; e < 4; e++) {
                    mma16(acc[mf][2 * e],     aq.x, aq.z, aq.y, aq.w, bq[e].x, bq[e].y);
                    mma16(acc[mf][2 * e + 1], aq.x, aq.z, aq.y, aq.w, bq[e].z, bq[e].w);
                }
            }
        }
    }

    // ---------------- epilogue ----------------
    const float nw = __ldg(nwp);
    float nz[4][2];
    #pragma unroll
    for (int mf = 0; mf < 4; mf++) {
        int gy = py0 + 4 * wm + mf;
        const float* np = noise + (size_t)b * 65536 + (size_t)gy * 256 + px0 + r;
        nz[mf][0] = nw * __ldg(np);
        nz[mf][1] = nw * __ldg(np + 8);
    }
    #pragma unroll
    for (int nf = 0; nf < 8; nf++) {
        int cp = wn * 64 + nf * 8 + 2 * j;       // even co of the pair
        float da, db, sa = 0.f, sb = 0.f;
        if (FIRST) {
            da = __ldg(g_d1 + b * 128 + cp); db = __ldg(g_d1 + b * 128 + cp + 1);
            sa = __ldg(g_style2 + b * 128 + cp); sb = __ldg(g_style2 + b * 128 + cp + 1);
        } else {
            da = __ldg(g_d2 + b * 128 + cp); db = __ldg(g_d2 + b * 128 + cp + 1);
        }
        #pragma unroll
        for (int mf = 0; mf < 4; mf++) {
            int gy = py0 + 4 * wm + mf;
            float v0 = da * acc[mf][nf][0] + nz[mf][0];
            float v1 = db * acc[mf][nf][1] + nz[mf][0];
            float v2 = da * acc[mf][nf][2] + nz[mf][1];
            float v3 = db * acc[mf][nf][3] + nz[mf][1];
            if (FIRST) {
                // write g_t NHWC fp16 (128 ch/px = 64 half2-words/px), permuted position
                int c16 = cp & 15;
                int word = 2 * ((c16 & 7) >> 1) + (c16 >> 3);   // half2-word within 16-group
                size_t pb = ((size_t)((b * 256 + gy) * 256) + px0 + r) * 64
                            + (cp >> 4) * 8 + word;
                __half2 h0 = __floats2half2_rn(lrelu(v0) * sa, lrelu(v1) * sb);
                __half2 h2 = __floats2half2_rn(lrelu(v2) * sa, lrelu(v3) * sb);
                *(__half2*)((__half*)g_t + pb * 2) = h0;
                *(__half2*)((__half*)g_t + (pb + 8 * 64) * 2) = h2;   // x+8 -> +8 px * 64 words
            } else {
                size_t ob = ((size_t)(b * 128 + cp) * 256 + gy) * 256 + px0 + r;
                outp[ob] = v0 * INV_SQRT2;
                outp[ob + 65536] = v1 * INV_SQRT2;        // co+1
                outp[ob + 8] = v2 * INV_SQRT2;            // x+8
                outp[ob + 65536 + 8] = v3 * INV_SQRT2;
            }
        }
    }
}

// ---------------- host ----------------
extern "C" void kernel_launch(void* const* d_in, const int* in_sizes, int n_in,
                              void* d_out, int out_size) {
    const float* x   = (const float*)d_in[0];
    const float* s   = (const float*)d_in[1];
    const float* noi = (const float*)d_in[2];
    const float* a1w = (const float*)d_in[3];
    const float* a1b = (const float*)d_in[4];
    const float* w1  = (const float*)d_in[5];
    const float* a2w = (const float*)d_in[6];
    const float* a2b = (const float*)d_in[7];
    const float* w2  = (const float*)d_in[8];
    const float* nw  = (const float*)d_in[9];
    const float* scw = (const float*)d_in[10];
    float* out = (float*)d_out;

    static bool attr_done = false;
    if (!attr_done) {
        cudaFuncSetAttribute(conv_fp16<64, true>,
                             cudaFuncAttributeMaxDynamicSharedMemorySize, SMEM_BYTES);
        cudaFuncSetAttribute(conv_fp16<128, false>,
                             cudaFuncAttributeMaxDynamicSharedMemorySize, SMEM_BYTES);
        attr_done = true;
    }

    // order chosen so conv1 is the 4th launch (ncu profiles launch #4)
    style_demod_kernel<<<dim3(BATCH, 16), 256>>>(s, a1w, a1b, a2w, a2b, w1, w2);
    prep_all_kernel<<<1120, 256>>>(w1, w2, scw);
    act_kernel<<<dim3(4, 256, 8), 256>>>(x);

    dim3 grid(HW / 16, HW / 8, BATCH);
    conv_fp16<64, true><<<grid, 128, SMEM_BYTES>>>(noi, nw, nullptr);
    conv_fp16<128, false><<<grid, 128, SMEM_BYTES>>>(noi, nw, out);
}